// round 15
// baseline (speedup 1.0000x reference)
#include <cuda_runtime.h>
#include <cstring>

// Fused JPEG round-trip, persistent-CTA version of the R8 champion.
// Grid = 444 CTAs (one wave on 148/152 SMs); each CTA processes ~4-5 tiles
// (256x8 px) with register double-buffer prefetch of the next tile's loads.
// Thread owns row r of ONE 8x8 block: Y scalar, U+V packed f32x2.
// Transposes via per-warp conflict-free smem.
// Input : d_in[0] = float32 [1,3,2048,2048]; Output: float32 [1,3*2048*2048]

#define IMG_W  2048
#define IMG_H  2048
#define PLANE  (IMG_W * IMG_H)
#define NTILES 2048          // 8 x-tiles * 256 y-tiles
#define GRID   444           // 3 * 148; single wave on 148 or 152 SMs

#define C1 0.4903926402f
#define C2 0.4619397663f
#define C3 0.4157348062f
#define C4 0.3535533906f
#define C5 0.2777851165f
#define C6 0.1913417162f
#define C7 0.0975451610f

__constant__ float cQf[128] = {
    16,11,10,16,24,40,51,61,  12,12,14,19,26,58,60,55,
    14,13,16,24,40,57,69,56,  14,17,22,29,51,87,80,62,
    18,22,37,56,68,109,103,77, 24,35,55,64,81,104,113,92,
    49,64,78,87,103,121,120,101, 72,92,95,98,112,100,103,99,
    17,18,24,47,99,99,99,99,  18,21,26,66,99,99,99,99,
    24,26,56,99,99,99,99,99,  47,66,99,99,99,99,99,99,
    99,99,99,99,99,99,99,99,  99,99,99,99,99,99,99,99,
    99,99,99,99,99,99,99,99,  99,99,99,99,99,99,99,99 };
__constant__ float cRQf[128] = {
    1.f/16,1.f/11,1.f/10,1.f/16,1.f/24,1.f/40,1.f/51,1.f/61,
    1.f/12,1.f/12,1.f/14,1.f/19,1.f/26,1.f/58,1.f/60,1.f/55,
    1.f/14,1.f/13,1.f/16,1.f/24,1.f/40,1.f/57,1.f/69,1.f/56,
    1.f/14,1.f/17,1.f/22,1.f/29,1.f/51,1.f/87,1.f/80,1.f/62,
    1.f/18,1.f/22,1.f/37,1.f/56,1.f/68,1.f/109,1.f/103,1.f/77,
    1.f/24,1.f/35,1.f/55,1.f/64,1.f/81,1.f/104,1.f/113,1.f/92,
    1.f/49,1.f/64,1.f/78,1.f/87,1.f/103,1.f/121,1.f/120,1.f/101,
    1.f/72,1.f/92,1.f/95,1.f/98,1.f/112,1.f/100,1.f/103,1.f/99,
    1.f/17,1.f/18,1.f/24,1.f/47,1.f/99,1.f/99,1.f/99,1.f/99,
    1.f/18,1.f/21,1.f/26,1.f/66,1.f/99,1.f/99,1.f/99,1.f/99,
    1.f/24,1.f/26,1.f/56,1.f/99,1.f/99,1.f/99,1.f/99,1.f/99,
    1.f/47,1.f/66,1.f/99,1.f/99,1.f/99,1.f/99,1.f/99,1.f/99,
    1.f/99,1.f/99,1.f/99,1.f/99,1.f/99,1.f/99,1.f/99,1.f/99,
    1.f/99,1.f/99,1.f/99,1.f/99,1.f/99,1.f/99,1.f/99,1.f/99,
    1.f/99,1.f/99,1.f/99,1.f/99,1.f/99,1.f/99,1.f/99,1.f/99,
    1.f/99,1.f/99,1.f/99,1.f/99,1.f/99,1.f/99,1.f/99,1.f/99 };

#define NC_A0 0.0158730159f
#define NC_B0 (-1.93476190e-8f)
#define NC_C0 0.0222539619f
#define NC_K0 (-4.8373935f)
#define NC_A1 0.0161030596f
#define NC_B1 (-0.0055416377f)
#define NC_C1 (-0.0114997768f)
#define NC_K1 0.2006247f
#define NC_A2 0.0149925037f
#define NC_B2 0.0265667181f
#define NC_C2 6.09145427e-9f
#define NC_K2 (-5.1081869f)

typedef unsigned long long ull;

__device__ __forceinline__ ull pk(float lo, float hi) {
    float2 t = make_float2(lo, hi); ull r; memcpy(&r, &t, 8); return r;
}
__device__ __forceinline__ ull pk1(float x) { return pk(x, x); }
__device__ __forceinline__ float2 unpk(ull a) {
    float2 t; memcpy(&t, &a, 8); return t;
}
__device__ __forceinline__ ull padd(ull a, ull b) {
    ull r; asm("add.rn.f32x2 %0,%1,%2;" : "=l"(r) : "l"(a), "l"(b)); return r;
}
__device__ __forceinline__ ull pmul(ull a, ull b) {
    ull r; asm("mul.rn.f32x2 %0,%1,%2;" : "=l"(r) : "l"(a), "l"(b)); return r;
}
__device__ __forceinline__ ull pfma(ull a, ull b, ull c) {
    ull r; asm("fma.rn.f32x2 %0,%1,%2,%3;" : "=l"(r) : "l"(a), "l"(b), "l"(c)); return r;
}
__device__ __forceinline__ ull psub(ull a, ull b) { return pfma(b, pk1(-1.0f), a); }

__device__ __forceinline__ void fdct8(float v[8]) {
    float e0=v[0]+v[7], e1=v[1]+v[6], e2=v[2]+v[5], e3=v[3]+v[4];
    float o0=v[0]-v[7], o1=v[1]-v[6], o2=v[2]-v[5], o3=v[3]-v[4];
    float s03=e0+e3, s12=e1+e2, d03=e0-e3, d12=e1-e2;
    v[0]=C4*(s03+s12);
    v[4]=C4*(s03-s12);
    v[2]=fmaf(C2,d03, C6*d12);
    v[6]=fmaf(C6,d03,-C2*d12);
    v[1]=fmaf(C1,o0,fmaf( C3,o1,fmaf( C5,o2, C7*o3)));
    v[3]=fmaf(C3,o0,fmaf(-C7,o1,fmaf(-C1,o2,-C5*o3)));
    v[5]=fmaf(C5,o0,fmaf(-C1,o1,fmaf( C7,o2, C3*o3)));
    v[7]=fmaf(C7,o0,fmaf(-C5,o1,fmaf( C3,o2,-C1*o3)));
}
__device__ __forceinline__ void idct8(float v[8]) {
    float sp=C4*(v[0]+v[4]), sm=C4*(v[0]-v[4]);
    float t1=fmaf(C2,v[2], C6*v[6]);
    float t2=fmaf(C6,v[2],-C2*v[6]);
    float E0=sp+t1, E1=sm+t2, E2=sm-t2, E3=sp-t1;
    float O0=fmaf(C1,v[1],fmaf( C3,v[3],fmaf( C5,v[5], C7*v[7])));
    float O1=fmaf(C3,v[1],fmaf(-C7,v[3],fmaf(-C1,v[5],-C5*v[7])));
    float O2=fmaf(C5,v[1],fmaf(-C1,v[3],fmaf( C7,v[5], C3*v[7])));
    float O3=fmaf(C7,v[1],fmaf(-C5,v[3],fmaf( C3,v[5],-C1*v[7])));
    v[0]=E0+O0; v[7]=E0-O0;
    v[1]=E1+O1; v[6]=E1-O1;
    v[2]=E2+O2; v[5]=E2-O2;
    v[3]=E3+O3; v[4]=E3-O3;
}
__device__ __forceinline__ void fdct8p(ull v[8]) {
    ull e0=padd(v[0],v[7]), e1=padd(v[1],v[6]), e2=padd(v[2],v[5]), e3=padd(v[3],v[4]);
    ull o0=psub(v[0],v[7]), o1=psub(v[1],v[6]), o2=psub(v[2],v[5]), o3=psub(v[3],v[4]);
    ull s03=padd(e0,e3), s12=padd(e1,e2), d03=psub(e0,e3), d12=psub(e1,e2);
    v[0]=pmul(pk1(C4), padd(s03,s12));
    v[4]=pmul(pk1(C4), psub(s03,s12));
    v[2]=pfma(pk1(C2),d03, pmul(pk1( C6),d12));
    v[6]=pfma(pk1(C6),d03, pmul(pk1(-C2),d12));
    v[1]=pfma(pk1(C1),o0, pfma(pk1( C3),o1, pfma(pk1( C5),o2, pmul(pk1( C7),o3))));
    v[3]=pfma(pk1(C3),o0, pfma(pk1(-C7),o1, pfma(pk1(-C1),o2, pmul(pk1(-C5),o3))));
    v[5]=pfma(pk1(C5),o0, pfma(pk1(-C1),o1, pfma(pk1( C7),o2, pmul(pk1( C3),o3))));
    v[7]=pfma(pk1(C7),o0, pfma(pk1(-C5),o1, pfma(pk1( C3),o2, pmul(pk1(-C1),o3))));
}
__device__ __forceinline__ void idct8p(ull v[8]) {
    ull sp=pmul(pk1(C4), padd(v[0],v[4]));
    ull sm=pmul(pk1(C4), psub(v[0],v[4]));
    ull t1=pfma(pk1(C2),v[2], pmul(pk1( C6),v[6]));
    ull t2=pfma(pk1(C6),v[2], pmul(pk1(-C2),v[6]));
    ull E0=padd(sp,t1), E1=padd(sm,t2), E2=psub(sm,t2), E3=psub(sp,t1);
    ull O0=pfma(pk1(C1),v[1], pfma(pk1( C3),v[3], pfma(pk1( C5),v[5], pmul(pk1( C7),v[7]))));
    ull O1=pfma(pk1(C3),v[1], pfma(pk1(-C7),v[3], pfma(pk1(-C1),v[5], pmul(pk1(-C5),v[7]))));
    ull O2=pfma(pk1(C5),v[1], pfma(pk1(-C1),v[3], pfma(pk1( C7),v[5], pmul(pk1( C3),v[7]))));
    ull O3=pfma(pk1(C7),v[1], pfma(pk1(-C5),v[3], pfma(pk1( C3),v[5], pmul(pk1(-C1),v[7]))));
    v[0]=padd(E0,O0); v[7]=psub(E0,O0);
    v[1]=padd(E1,O1); v[6]=psub(E1,O1);
    v[2]=padd(E2,O2); v[5]=psub(E2,O2);
    v[3]=padd(E3,O3); v[4]=psub(E3,O3);
}

// smem layouts (conflict-free, validated R8-R14)
#define RPY 12
#define GPY 104
#define RPU 10
#define GPU 84

__device__ __forceinline__ void writeY(const float vy[8], float* ybg, int r) {
    float* yw = ybg + RPY * r;
    *(float4*)(yw)     = make_float4(vy[0], vy[1], vy[2], vy[3]);
    *(float4*)(yw + 4) = make_float4(vy[4], vy[5], vy[6], vy[7]);
}
__device__ __forceinline__ void writeUV(const ull uv[8], ull* uvbg, int r) {
    ull* uw = uvbg + RPU * r;
    #pragma unroll
    for (int k = 0; k < 8; k += 2)
        *(ulonglong2*)(uw + k) = make_ulonglong2(uv[k], uv[k+1]);
}
__device__ __forceinline__ void readY(float vy[8], const float* ybg, int r) {
    #pragma unroll
    for (int k = 0; k < 8; ++k) vy[k] = ybg[RPY * k + r];
}
__device__ __forceinline__ void readUV(ull uv[8], const ull* uvbg, int r) {
    #pragma unroll
    for (int k = 0; k < 8; ++k) uv[k] = uvbg[RPU * k + r];
}

struct TileBuf { float4 v[6]; };   // Ra,Rb,Ga,Gb,Ba,Bb for this thread's row

__device__ __forceinline__ int tile_base(int t, int grp, int r) {
    int bx = t & 7;           // 8 x-tiles
    int by = t >> 3;          // 256 y-tiles
    return (by * 8 + r) * IMG_W + bx * 256 + grp * 8;
}

__device__ __forceinline__ void loadTile(TileBuf& b, const float* __restrict__ in, int base) {
    b.v[0] = *(const float4*)(in + base);
    b.v[1] = *(const float4*)(in + base + 4);
    b.v[2] = *(const float4*)(in + base + PLANE);
    b.v[3] = *(const float4*)(in + base + PLANE + 4);
    b.v[4] = *(const float4*)(in + base + 2*PLANE);
    b.v[5] = *(const float4*)(in + base + 2*PLANE + 4);
}

__device__ __forceinline__ void processTile(
    const TileBuf& tb, float* __restrict__ out, int base,
    float* ybg, ull* uvbg, const float* qt, int r)
{
    float R[8] = {tb.v[0].x,tb.v[0].y,tb.v[0].z,tb.v[0].w, tb.v[1].x,tb.v[1].y,tb.v[1].z,tb.v[1].w};
    float G[8] = {tb.v[2].x,tb.v[2].y,tb.v[2].z,tb.v[2].w, tb.v[3].x,tb.v[3].y,tb.v[3].z,tb.v[3].w};
    float B[8] = {tb.v[4].x,tb.v[4].y,tb.v[4].z,tb.v[4].w, tb.v[5].x,tb.v[5].y,tb.v[5].z,tb.v[5].w};

    float vY[8];
    ull   pUV[8];
    #pragma unroll
    for (int k = 0; k < 8; ++k) {
        vY[k] = 0.299f*R[k] + 0.587f*G[k] + 0.114f*B[k];
        float u = fmaf(-0.168736f, R[k], fmaf(-0.331264f, G[k], fmaf(0.5f, B[k], 128.0f)));
        float v = fmaf(0.5f, R[k], fmaf(-0.418688f, G[k], fmaf(-0.081312f, B[k], 128.0f)));
        pUV[k] = pk(u, v);
    }

    // stage 1: row DCT + transpose (syncwarp guards prev iteration's reads)
    fdct8(vY);
    fdct8p(pUV);
    __syncwarp();
    writeY(vY, ybg, r);
    writeUV(pUV, uvbg, r);
    __syncwarp();
    readY(vY, ybg, r);
    readUV(pUV, uvbg, r);

    // stage 2: column DCT + quant/dequant + column IDCT
    fdct8(vY);
    #pragma unroll
    for (int i = 0; i < 8; ++i) {
        float2 qy = *(const float2*)(qt + i * 16 + r * 2);
        float sv = vY[i];
        float d  = sv * qy.y;
        float rn = rintf(d);
        float e  = fmaf(-rn, qy.x, sv) * qy.y;
        vY[i]    = fmaf(e*e, e, rn) * qy.x;
    }
    idct8(vY);
    __syncwarp();            // stage-1 reads done in all lanes before overwrite
    writeY(vY, ybg, r);

    fdct8p(pUV);
    #pragma unroll
    for (int i = 0; i < 8; ++i) {
        float2 qc = *(const float2*)(qt + 128 + i * 16 + r * 2);
        float2 s = unpk(pUV[i]);
        float d0 = s.x * qc.y, d1 = s.y * qc.y;
        float r0 = rintf(d0), r1 = rintf(d1);
        float e0 = fmaf(-r0, qc.x, s.x) * qc.y;
        float e1 = fmaf(-r1, qc.x, s.y) * qc.y;
        pUV[i] = pk(fmaf(e0*e0, e0, r0) * qc.x,
                    fmaf(e1*e1, e1, r1) * qc.x);
    }
    idct8p(pUV);
    writeUV(pUV, uvbg, r);
    __syncwarp();
    readY(vY, ybg, r);
    readUV(pUV, uvbg, r);

    // stage 4: row IDCT
    idct8(vY);
    idct8p(pUV);

    // folded inverse color + normalize + store
    #pragma unroll
    for (int h = 0; h < 2; ++h) {
        float4 Ro, Go, Bo;
        #pragma unroll
        for (int k = 0; k < 4; ++k) {
            int c = h*4 + k;
            float yv = vY[c];
            float2 uvv = unpk(pUV[c]);
            float u = uvv.x, v = uvv.y;
            ((float*)&Ro)[k] = fmaf(yv, NC_A0, fmaf(u, NC_B0, fmaf(v, NC_C0, NC_K0)));
            ((float*)&Go)[k] = fmaf(yv, NC_A1, fmaf(u, NC_B1, fmaf(v, NC_C1, NC_K1)));
            ((float*)&Bo)[k] = fmaf(yv, NC_A2, fmaf(u, NC_B2, fmaf(v, NC_C2, NC_K2)));
        }
        *(float4*)(out + base + h*4)           = Ro;
        *(float4*)(out + base + PLANE + h*4)   = Go;
        *(float4*)(out + base + 2*PLANE + h*4) = Bo;
    }
}

__global__ __launch_bounds__(256, 3)
void jpeg_roundtrip_kernel(const float* __restrict__ in, float* __restrict__ out)
{
    __shared__ __align__(16) float yb[8 * 4 * GPY];   // 13312 B
    __shared__ __align__(16) ull  uvb[8 * 4 * GPU];   // 21504 B
    __shared__ float qt[256];                         // interleaved (q, rq)

    const int tid  = threadIdx.x;
    const int warp = tid >> 5;
    const int lane = tid & 31;
    const int r    = lane >> 2;
    const int g    = lane & 3;

    {   // build interleaved quant table
        int w  = tid & 1, rr = (tid >> 1) & 7, ii = (tid >> 4) & 7, ch = tid >> 7;
        int si = ch * 64 + ii * 8 + rr;
        qt[tid] = w ? cRQf[si] : cQf[si];
    }

    float* ybg  = yb  + (warp * 4 + g) * GPY;
    ull*   uvbg = uvb + (warp * 4 + g) * GPU;
    const int grp = warp * 4 + g;

    // persistent ping-pong over tiles bid, bid+GRID, ...
    TileBuf A, B;
    int t0 = blockIdx.x;
    loadTile(A, in, tile_base(t0, grp, r));
    __syncthreads();   // quant table ready

    for (;;) {
        int t1 = t0 + GRID;
        bool m1 = (t1 < NTILES);
        if (m1) loadTile(B, in, tile_base(t1, grp, r));
        processTile(A, out, tile_base(t0, grp, r), ybg, uvbg, qt, r);
        if (!m1) break;

        int t2 = t1 + GRID;
        bool m2 = (t2 < NTILES);
        if (m2) loadTile(A, in, tile_base(t2, grp, r));
        processTile(B, out, tile_base(t1, grp, r), ybg, uvbg, qt, r);
        if (!m2) break;
        t0 = t2;
    }
}

extern "C" void kernel_launch(void* const* d_in, const int* in_sizes, int n_in,
                              void* d_out, int out_size)
{
    const float* in = (const float*)d_in[0];
    float* out = (float*)d_out;
    jpeg_roundtrip_kernel<<<GRID, 256>>>(in, out);
}

// round 16
// speedup vs baseline: 1.0664x; 1.0664x over previous
#include <cuda_runtime.h>
#include <cstring>

// Fused JPEG round-trip (R8 champion skeleton + fma-cycle trims).
// Thread owns row r of ONE 8x8 block: Y scalar, U+V packed f32x2.
// Fwd color in JPEG difference form (packed UV), fully packed quant with
// magic-number round-half-even, transposes via conflict-free per-warp smem.
// Input : d_in[0] = float32 [1,3,2048,2048]; Output: float32 [1,3*2048*2048]

#define IMG_W  2048
#define IMG_H  2048
#define PLANE  (IMG_W * IMG_H)

#define C1 0.4903926402f
#define C2 0.4619397663f
#define C3 0.4157348062f
#define C4 0.3535533906f
#define C5 0.2777851165f
#define C6 0.1913417162f
#define C7 0.0975451610f

#define MAGICF 12582912.0f   // 1.5*2^23: (d+M)-M == rint(d) for |d| < 2^22

__constant__ float cQf[128] = {
    16,11,10,16,24,40,51,61,  12,12,14,19,26,58,60,55,
    14,13,16,24,40,57,69,56,  14,17,22,29,51,87,80,62,
    18,22,37,56,68,109,103,77, 24,35,55,64,81,104,113,92,
    49,64,78,87,103,121,120,101, 72,92,95,98,112,100,103,99,
    17,18,24,47,99,99,99,99,  18,21,26,66,99,99,99,99,
    24,26,56,99,99,99,99,99,  47,66,99,99,99,99,99,99,
    99,99,99,99,99,99,99,99,  99,99,99,99,99,99,99,99,
    99,99,99,99,99,99,99,99,  99,99,99,99,99,99,99,99 };
__constant__ float cRQf[128] = {
    1.f/16,1.f/11,1.f/10,1.f/16,1.f/24,1.f/40,1.f/51,1.f/61,
    1.f/12,1.f/12,1.f/14,1.f/19,1.f/26,1.f/58,1.f/60,1.f/55,
    1.f/14,1.f/13,1.f/16,1.f/24,1.f/40,1.f/57,1.f/69,1.f/56,
    1.f/14,1.f/17,1.f/22,1.f/29,1.f/51,1.f/87,1.f/80,1.f/62,
    1.f/18,1.f/22,1.f/37,1.f/56,1.f/68,1.f/109,1.f/103,1.f/77,
    1.f/24,1.f/35,1.f/55,1.f/64,1.f/81,1.f/104,1.f/113,1.f/92,
    1.f/49,1.f/64,1.f/78,1.f/87,1.f/103,1.f/121,1.f/120,1.f/101,
    1.f/72,1.f/92,1.f/95,1.f/98,1.f/112,1.f/100,1.f/103,1.f/99,
    1.f/17,1.f/18,1.f/24,1.f/47,1.f/99,1.f/99,1.f/99,1.f/99,
    1.f/18,1.f/21,1.f/26,1.f/66,1.f/99,1.f/99,1.f/99,1.f/99,
    1.f/24,1.f/26,1.f/56,1.f/99,1.f/99,1.f/99,1.f/99,1.f/99,
    1.f/47,1.f/66,1.f/99,1.f/99,1.f/99,1.f/99,1.f/99,1.f/99,
    1.f/99,1.f/99,1.f/99,1.f/99,1.f/99,1.f/99,1.f/99,1.f/99,
    1.f/99,1.f/99,1.f/99,1.f/99,1.f/99,1.f/99,1.f/99,1.f/99,
    1.f/99,1.f/99,1.f/99,1.f/99,1.f/99,1.f/99,1.f/99,1.f/99,
    1.f/99,1.f/99,1.f/99,1.f/99,1.f/99,1.f/99,1.f/99,1.f/99 };

#define NC_A0 0.0158730159f
#define NC_B0 (-1.93476190e-8f)
#define NC_C0 0.0222539619f
#define NC_K0 (-4.8373935f)
#define NC_A1 0.0161030596f
#define NC_B1 (-0.0055416377f)
#define NC_C1 (-0.0114997768f)
#define NC_K1 0.2006247f
#define NC_A2 0.0149925037f
#define NC_B2 0.0265667181f
#define NC_C2 6.09145427e-9f
#define NC_K2 (-5.1081869f)

typedef unsigned long long ull;

__device__ __forceinline__ ull pk(float lo, float hi) {
    float2 t = make_float2(lo, hi); ull r; memcpy(&r, &t, 8); return r;
}
__device__ __forceinline__ ull pk1(float x) { return pk(x, x); }
__device__ __forceinline__ float2 unpk(ull a) {
    float2 t; memcpy(&t, &a, 8); return t;
}
__device__ __forceinline__ ull padd(ull a, ull b) {
    ull r; asm("add.rn.f32x2 %0,%1,%2;" : "=l"(r) : "l"(a), "l"(b)); return r;
}
__device__ __forceinline__ ull pmul(ull a, ull b) {
    ull r; asm("mul.rn.f32x2 %0,%1,%2;" : "=l"(r) : "l"(a), "l"(b)); return r;
}
__device__ __forceinline__ ull pfma(ull a, ull b, ull c) {
    ull r; asm("fma.rn.f32x2 %0,%1,%2,%3;" : "=l"(r) : "l"(a), "l"(b), "l"(c)); return r;
}
__device__ __forceinline__ ull psub(ull a, ull b) { return pfma(b, pk1(-1.0f), a); }

__device__ __forceinline__ void fdct8(float v[8]) {
    float e0=v[0]+v[7], e1=v[1]+v[6], e2=v[2]+v[5], e3=v[3]+v[4];
    float o0=v[0]-v[7], o1=v[1]-v[6], o2=v[2]-v[5], o3=v[3]-v[4];
    float s03=e0+e3, s12=e1+e2, d03=e0-e3, d12=e1-e2;
    v[0]=C4*(s03+s12);
    v[4]=C4*(s03-s12);
    v[2]=fmaf(C2,d03, C6*d12);
    v[6]=fmaf(C6,d03,-C2*d12);
    v[1]=fmaf(C1,o0,fmaf( C3,o1,fmaf( C5,o2, C7*o3)));
    v[3]=fmaf(C3,o0,fmaf(-C7,o1,fmaf(-C1,o2,-C5*o3)));
    v[5]=fmaf(C5,o0,fmaf(-C1,o1,fmaf( C7,o2, C3*o3)));
    v[7]=fmaf(C7,o0,fmaf(-C5,o1,fmaf( C3,o2,-C1*o3)));
}
__device__ __forceinline__ void idct8(float v[8]) {
    float sp=C4*(v[0]+v[4]), sm=C4*(v[0]-v[4]);
    float t1=fmaf(C2,v[2], C6*v[6]);
    float t2=fmaf(C6,v[2],-C2*v[6]);
    float E0=sp+t1, E1=sm+t2, E2=sm-t2, E3=sp-t1;
    float O0=fmaf(C1,v[1],fmaf( C3,v[3],fmaf( C5,v[5], C7*v[7])));
    float O1=fmaf(C3,v[1],fmaf(-C7,v[3],fmaf(-C1,v[5],-C5*v[7])));
    float O2=fmaf(C5,v[1],fmaf(-C1,v[3],fmaf( C7,v[5], C3*v[7])));
    float O3=fmaf(C7,v[1],fmaf(-C5,v[3],fmaf( C3,v[5],-C1*v[7])));
    v[0]=E0+O0; v[7]=E0-O0;
    v[1]=E1+O1; v[6]=E1-O1;
    v[2]=E2+O2; v[5]=E2-O2;
    v[3]=E3+O3; v[4]=E3-O3;
}
__device__ __forceinline__ void fdct8p(ull v[8]) {
    ull e0=padd(v[0],v[7]), e1=padd(v[1],v[6]), e2=padd(v[2],v[5]), e3=padd(v[3],v[4]);
    ull o0=psub(v[0],v[7]), o1=psub(v[1],v[6]), o2=psub(v[2],v[5]), o3=psub(v[3],v[4]);
    ull s03=padd(e0,e3), s12=padd(e1,e2), d03=psub(e0,e3), d12=psub(e1,e2);
    v[0]=pmul(pk1(C4), padd(s03,s12));
    v[4]=pmul(pk1(C4), psub(s03,s12));
    v[2]=pfma(pk1(C2),d03, pmul(pk1( C6),d12));
    v[6]=pfma(pk1(C6),d03, pmul(pk1(-C2),d12));
    v[1]=pfma(pk1(C1),o0, pfma(pk1( C3),o1, pfma(pk1( C5),o2, pmul(pk1( C7),o3))));
    v[3]=pfma(pk1(C3),o0, pfma(pk1(-C7),o1, pfma(pk1(-C1),o2, pmul(pk1(-C5),o3))));
    v[5]=pfma(pk1(C5),o0, pfma(pk1(-C1),o1, pfma(pk1( C7),o2, pmul(pk1( C3),o3))));
    v[7]=pfma(pk1(C7),o0, pfma(pk1(-C5),o1, pfma(pk1( C3),o2, pmul(pk1(-C1),o3))));
}
__device__ __forceinline__ void idct8p(ull v[8]) {
    ull sp=pmul(pk1(C4), padd(v[0],v[4]));
    ull sm=pmul(pk1(C4), psub(v[0],v[4]));
    ull t1=pfma(pk1(C2),v[2], pmul(pk1( C6),v[6]));
    ull t2=pfma(pk1(C6),v[2], pmul(pk1(-C2),v[6]));
    ull E0=padd(sp,t1), E1=padd(sm,t2), E2=psub(sm,t2), E3=psub(sp,t1);
    ull O0=pfma(pk1(C1),v[1], pfma(pk1( C3),v[3], pfma(pk1( C5),v[5], pmul(pk1( C7),v[7]))));
    ull O1=pfma(pk1(C3),v[1], pfma(pk1(-C7),v[3], pfma(pk1(-C1),v[5], pmul(pk1(-C5),v[7]))));
    ull O2=pfma(pk1(C5),v[1], pfma(pk1(-C1),v[3], pfma(pk1( C7),v[5], pmul(pk1( C3),v[7]))));
    ull O3=pfma(pk1(C7),v[1], pfma(pk1(-C5),v[3], pfma(pk1( C3),v[5], pmul(pk1(-C1),v[7]))));
    v[0]=padd(E0,O0); v[7]=psub(E0,O0);
    v[1]=padd(E1,O1); v[6]=psub(E1,O1);
    v[2]=padd(E2,O2); v[5]=psub(E2,O2);
    v[3]=padd(E3,O3); v[4]=psub(E3,O3);
}

// smem layouts (conflict-free, validated R8-R15)
#define RPY 12
#define GPY 104
#define RPU 10
#define GPU 84

__device__ __forceinline__ void writeY(const float vy[8], float* ybg, int r) {
    float* yw = ybg + RPY * r;
    *(float4*)(yw)     = make_float4(vy[0], vy[1], vy[2], vy[3]);
    *(float4*)(yw + 4) = make_float4(vy[4], vy[5], vy[6], vy[7]);
}
__device__ __forceinline__ void writeUV(const ull uv[8], ull* uvbg, int r) {
    ull* uw = uvbg + RPU * r;
    #pragma unroll
    for (int k = 0; k < 8; k += 2)
        *(ulonglong2*)(uw + k) = make_ulonglong2(uv[k], uv[k+1]);
}
__device__ __forceinline__ void readY(float vy[8], const float* ybg, int r) {
    #pragma unroll
    for (int k = 0; k < 8; ++k) vy[k] = ybg[RPY * k + r];
}
__device__ __forceinline__ void readUV(ull uv[8], const ull* uvbg, int r) {
    #pragma unroll
    for (int k = 0; k < 8; ++k) uv[k] = uvbg[RPU * k + r];
}

__global__ __launch_bounds__(256, 4)
void jpeg_roundtrip_kernel(const float* __restrict__ in, float* __restrict__ out)
{
    __shared__ __align__(16) float yb[8 * 4 * GPY];   // 13312 B
    __shared__ __align__(16) ull  uvb[8 * 4 * GPU];   // 21504 B
    __shared__ float qtc[128];                        // chroma (q, rq) at [i*16 + r*2]
    __shared__ ull  ypq[32], yprq[32];                // luma i-pair packed tables

    const int tid  = threadIdx.x;
    const int warp = tid >> 5;
    const int lane = tid & 31;
    const int r    = lane >> 2;
    const int g    = lane & 3;

    {   // build quant tables
        if (tid < 128) {   // chroma interleaved (q, rq)
            int w = tid & 1, rr = (tid >> 1) & 7, ii = (tid >> 4) & 7;
            int si = 64 + ii * 8 + rr;
            qtc[tid] = w ? cRQf[si] : cQf[si];
        } else if (tid < 160) {   // luma q pairs: pk(Q[2j][rr], Q[2j+1][rr])
            int t = tid - 128, j = t >> 3, rr = t & 7;
            ypq[t] = pk(cQf[(2*j) * 8 + rr], cQf[(2*j+1) * 8 + rr]);
        } else if (tid < 192) {   // luma rq pairs
            int t = tid - 160, j = t >> 3, rr = t & 7;
            yprq[t] = pk(cRQf[(2*j) * 8 + rr], cRQf[(2*j+1) * 8 + rr]);
        }
    }

    float* ybg  = yb  + (warp * 4 + g) * GPY;
    ull*   uvbg = uvb + (warp * 4 + g) * GPU;

    const int x0   = blockIdx.x * 256 + (warp * 4 + g) * 8;
    const int y    = blockIdx.y * 8 + r;
    const int base = y * IMG_W + x0;

    const ull MG   = pk1(MAGICF);
    const ull CUV  = pk(0.5643341f, 0.7132668f);   // 0.5/(1-0.114), 0.5/(1-0.299)
    const ull K128 = pk1(128.0f);

    float vY[8];
    ull   pUV[8];

    // ---- load RGB + forward color (JPEG difference form) ----
    {
        const float4 Ra = *(const float4*)(in + base);
        const float4 Rb = *(const float4*)(in + base + 4);
        const float4 Ga = *(const float4*)(in + base + PLANE);
        const float4 Gb = *(const float4*)(in + base + PLANE + 4);
        const float4 Ba = *(const float4*)(in + base + 2*PLANE);
        const float4 Bb = *(const float4*)(in + base + 2*PLANE + 4);

        __syncthreads();   // quant tables ready

        float R[8] = {Ra.x,Ra.y,Ra.z,Ra.w, Rb.x,Rb.y,Rb.z,Rb.w};
        float G[8] = {Ga.x,Ga.y,Ga.z,Ga.w, Gb.x,Gb.y,Gb.z,Gb.w};
        float B[8] = {Ba.x,Ba.y,Ba.z,Ba.w, Bb.x,Bb.y,Bb.z,Bb.w};
        #pragma unroll
        for (int k = 0; k < 8; ++k) {
            float yv = 0.299f*R[k] + 0.587f*G[k] + 0.114f*B[k];
            vY[k] = yv;
            // U = cu*(B-Y)+128, V = cv*(R-Y)+128 (one packed fma)
            pUV[k] = pfma(pk(B[k] - yv, R[k] - yv), CUV, K128);
        }
    }

    // ---- stage 1: row DCT + transpose ----
    fdct8(vY);   writeY(vY, ybg, r);
    fdct8p(pUV); writeUV(pUV, uvbg, r);
    __syncwarp();
    readY(vY, ybg, r);
    readUV(pUV, uvbg, r);

    // ---- stage 2: column DCT + packed quant/dequant + column IDCT ----
    fdct8(vY);
    #pragma unroll
    for (int j = 0; j < 4; ++j) {     // luma packed over i-pairs
        ull q2  = ypq[j * 8 + r];
        ull rq2 = yprq[j * 8 + r];
        ull Yp  = pk(vY[2*j], vY[2*j+1]);
        ull d   = pmul(Yp, rq2);
        ull rn  = psub(padd(d, MG), MG);          // round-half-even
        ull e   = pmul(psub(Yp, pmul(rn, q2)), rq2);
        ull o   = pmul(pfma(pmul(e, e), e, rn), q2);
        float2 t = unpk(o);
        vY[2*j] = t.x; vY[2*j+1] = t.y;
    }
    idct8(vY);
    __syncwarp();            // stage-1 reads done in all lanes before overwrite
    writeY(vY, ybg, r);

    fdct8p(pUV);
    #pragma unroll
    for (int i = 0; i < 8; ++i) {     // chroma packed (U,V share constants)
        float2 qq = *(const float2*)(qtc + i * 16 + r * 2);
        ull q2  = pk1(qq.x);
        ull rq2 = pk1(qq.y);
        ull d   = pmul(pUV[i], rq2);
        ull rn  = psub(padd(d, MG), MG);
        ull e   = pmul(psub(pUV[i], pmul(rn, q2)), rq2);
        pUV[i]  = pmul(pfma(pmul(e, e), e, rn), q2);
    }
    idct8p(pUV);
    writeUV(pUV, uvbg, r);
    __syncwarp();
    readY(vY, ybg, r);
    readUV(pUV, uvbg, r);

    // ---- stage 4: row IDCT ----
    idct8(vY);
    idct8p(pUV);

    // ---- folded inverse color + normalize + store ----
    #pragma unroll
    for (int h = 0; h < 2; ++h) {
        float4 Ro, Go, Bo;
        #pragma unroll
        for (int k = 0; k < 4; ++k) {
            int c = h*4 + k;
            float yv = vY[c];
            float2 uvv = unpk(pUV[c]);
            float u = uvv.x, v = uvv.y;
            ((float*)&Ro)[k] = fmaf(yv, NC_A0, fmaf(u, NC_B0, fmaf(v, NC_C0, NC_K0)));
            ((float*)&Go)[k] = fmaf(yv, NC_A1, fmaf(u, NC_B1, fmaf(v, NC_C1, NC_K1)));
            ((float*)&Bo)[k] = fmaf(yv, NC_A2, fmaf(u, NC_B2, fmaf(v, NC_C2, NC_K2)));
        }
        *(float4*)(out + base + h*4)           = Ro;
        *(float4*)(out + base + PLANE + h*4)   = Go;
        *(float4*)(out + base + 2*PLANE + h*4) = Bo;
    }
}

extern "C" void kernel_launch(void* const* d_in, const int* in_sizes, int n_in,
                              void* d_out, int out_size)
{
    const float* in = (const float*)d_in[0];
    float* out = (float*)d_out;
    dim3 grid(IMG_W / 256, IMG_H / 8);
    jpeg_roundtrip_kernel<<<grid, 256>>>(in, out);
}

// round 17
// speedup vs baseline: 1.1163x; 1.0468x over previous
#include <cuda_runtime.h>
#include <cstring>

// Fused JPEG round-trip — FINAL (R8 champion, 23.0us, rel_err 3.6e-7).
// Thread owns row r of ONE 8x8 block: Y scalar (8 regs), U+V packed f32x2
// (16 regs). Transposes via per-warp conflict-free smem. 4 CTAs/SM.
// Input : d_in[0] = float32 [1,3,2048,2048]; Output: float32 [1,3*2048*2048]

#define IMG_W  2048
#define IMG_H  2048
#define PLANE  (IMG_W * IMG_H)

#define C1 0.4903926402f
#define C2 0.4619397663f
#define C3 0.4157348062f
#define C4 0.3535533906f
#define C5 0.2777851165f
#define C6 0.1913417162f
#define C7 0.0975451610f

__constant__ float cQf[128] = {
    16,11,10,16,24,40,51,61,  12,12,14,19,26,58,60,55,
    14,13,16,24,40,57,69,56,  14,17,22,29,51,87,80,62,
    18,22,37,56,68,109,103,77, 24,35,55,64,81,104,113,92,
    49,64,78,87,103,121,120,101, 72,92,95,98,112,100,103,99,
    17,18,24,47,99,99,99,99,  18,21,26,66,99,99,99,99,
    24,26,56,99,99,99,99,99,  47,66,99,99,99,99,99,99,
    99,99,99,99,99,99,99,99,  99,99,99,99,99,99,99,99,
    99,99,99,99,99,99,99,99,  99,99,99,99,99,99,99,99 };
__constant__ float cRQf[128] = {
    1.f/16,1.f/11,1.f/10,1.f/16,1.f/24,1.f/40,1.f/51,1.f/61,
    1.f/12,1.f/12,1.f/14,1.f/19,1.f/26,1.f/58,1.f/60,1.f/55,
    1.f/14,1.f/13,1.f/16,1.f/24,1.f/40,1.f/57,1.f/69,1.f/56,
    1.f/14,1.f/17,1.f/22,1.f/29,1.f/51,1.f/87,1.f/80,1.f/62,
    1.f/18,1.f/22,1.f/37,1.f/56,1.f/68,1.f/109,1.f/103,1.f/77,
    1.f/24,1.f/35,1.f/55,1.f/64,1.f/81,1.f/104,1.f/113,1.f/92,
    1.f/49,1.f/64,1.f/78,1.f/87,1.f/103,1.f/121,1.f/120,1.f/101,
    1.f/72,1.f/92,1.f/95,1.f/98,1.f/112,1.f/100,1.f/103,1.f/99,
    1.f/17,1.f/18,1.f/24,1.f/47,1.f/99,1.f/99,1.f/99,1.f/99,
    1.f/18,1.f/21,1.f/26,1.f/66,1.f/99,1.f/99,1.f/99,1.f/99,
    1.f/24,1.f/26,1.f/56,1.f/99,1.f/99,1.f/99,1.f/99,1.f/99,
    1.f/47,1.f/66,1.f/99,1.f/99,1.f/99,1.f/99,1.f/99,1.f/99,
    1.f/99,1.f/99,1.f/99,1.f/99,1.f/99,1.f/99,1.f/99,1.f/99,
    1.f/99,1.f/99,1.f/99,1.f/99,1.f/99,1.f/99,1.f/99,1.f/99,
    1.f/99,1.f/99,1.f/99,1.f/99,1.f/99,1.f/99,1.f/99,1.f/99,
    1.f/99,1.f/99,1.f/99,1.f/99,1.f/99,1.f/99,1.f/99,1.f/99 };

// inv(W)
#define IW01 (-1.2189e-6f)
#define IW02  1.4019996f
#define IW11 (-0.34413570f)
#define IW12 (-0.71413614f)
#define IW21  1.7720001f
#define IW22  4.0630e-7f
#define MEAN0 0.49137255f
#define MEAN1 0.48235294f
#define MEAN2 0.44666666f
#define ISTD0 4.04761905f
#define ISTD1 4.10628019f
#define ISTD2 3.82308846f

typedef unsigned long long ull;

// ---- packed f32x2 helpers ----
__device__ __forceinline__ ull pk(float lo, float hi) {
    float2 t = make_float2(lo, hi); ull r; memcpy(&r, &t, 8); return r;
}
__device__ __forceinline__ ull pk1(float x) { return pk(x, x); }
__device__ __forceinline__ float2 unpk(ull a) {
    float2 t; memcpy(&t, &a, 8); return t;
}
__device__ __forceinline__ ull padd(ull a, ull b) {
    ull r; asm("add.rn.f32x2 %0,%1,%2;" : "=l"(r) : "l"(a), "l"(b)); return r;
}
__device__ __forceinline__ ull pmul(ull a, ull b) {
    ull r; asm("mul.rn.f32x2 %0,%1,%2;" : "=l"(r) : "l"(a), "l"(b)); return r;
}
__device__ __forceinline__ ull pfma(ull a, ull b, ull c) {
    ull r; asm("fma.rn.f32x2 %0,%1,%2,%3;" : "=l"(r) : "l"(a), "l"(b), "l"(c)); return r;
}
__device__ __forceinline__ ull psub(ull a, ull b) { return pfma(b, pk1(-1.0f), a); }

// ---- scalar 8-pt transforms ----
__device__ __forceinline__ void fdct8(float v[8]) {
    float e0=v[0]+v[7], e1=v[1]+v[6], e2=v[2]+v[5], e3=v[3]+v[4];
    float o0=v[0]-v[7], o1=v[1]-v[6], o2=v[2]-v[5], o3=v[3]-v[4];
    float s03=e0+e3, s12=e1+e2, d03=e0-e3, d12=e1-e2;
    v[0]=C4*(s03+s12);
    v[4]=C4*(s03-s12);
    v[2]=fmaf(C2,d03, C6*d12);
    v[6]=fmaf(C6,d03,-C2*d12);
    v[1]=fmaf(C1,o0,fmaf( C3,o1,fmaf( C5,o2, C7*o3)));
    v[3]=fmaf(C3,o0,fmaf(-C7,o1,fmaf(-C1,o2,-C5*o3)));
    v[5]=fmaf(C5,o0,fmaf(-C1,o1,fmaf( C7,o2, C3*o3)));
    v[7]=fmaf(C7,o0,fmaf(-C5,o1,fmaf( C3,o2,-C1*o3)));
}
__device__ __forceinline__ void idct8(float v[8]) {
    float sp=C4*(v[0]+v[4]), sm=C4*(v[0]-v[4]);
    float t1=fmaf(C2,v[2], C6*v[6]);
    float t2=fmaf(C6,v[2],-C2*v[6]);
    float E0=sp+t1, E1=sm+t2, E2=sm-t2, E3=sp-t1;
    float O0=fmaf(C1,v[1],fmaf( C3,v[3],fmaf( C5,v[5], C7*v[7])));
    float O1=fmaf(C3,v[1],fmaf(-C7,v[3],fmaf(-C1,v[5],-C5*v[7])));
    float O2=fmaf(C5,v[1],fmaf(-C1,v[3],fmaf( C7,v[5], C3*v[7])));
    float O3=fmaf(C7,v[1],fmaf(-C5,v[3],fmaf( C3,v[5],-C1*v[7])));
    v[0]=E0+O0; v[7]=E0-O0;
    v[1]=E1+O1; v[6]=E1-O1;
    v[2]=E2+O2; v[5]=E2-O2;
    v[3]=E3+O3; v[4]=E3-O3;
}

// ---- packed 8-pt transforms ----
__device__ __forceinline__ void fdct8p(ull v[8]) {
    ull e0=padd(v[0],v[7]), e1=padd(v[1],v[6]), e2=padd(v[2],v[5]), e3=padd(v[3],v[4]);
    ull o0=psub(v[0],v[7]), o1=psub(v[1],v[6]), o2=psub(v[2],v[5]), o3=psub(v[3],v[4]);
    ull s03=padd(e0,e3), s12=padd(e1,e2), d03=psub(e0,e3), d12=psub(e1,e2);
    v[0]=pmul(pk1(C4), padd(s03,s12));
    v[4]=pmul(pk1(C4), psub(s03,s12));
    v[2]=pfma(pk1(C2),d03, pmul(pk1( C6),d12));
    v[6]=pfma(pk1(C6),d03, pmul(pk1(-C2),d12));
    v[1]=pfma(pk1(C1),o0, pfma(pk1( C3),o1, pfma(pk1( C5),o2, pmul(pk1( C7),o3))));
    v[3]=pfma(pk1(C3),o0, pfma(pk1(-C7),o1, pfma(pk1(-C1),o2, pmul(pk1(-C5),o3))));
    v[5]=pfma(pk1(C5),o0, pfma(pk1(-C1),o1, pfma(pk1( C7),o2, pmul(pk1( C3),o3))));
    v[7]=pfma(pk1(C7),o0, pfma(pk1(-C5),o1, pfma(pk1( C3),o2, pmul(pk1(-C1),o3))));
}
__device__ __forceinline__ void idct8p(ull v[8]) {
    ull sp=pmul(pk1(C4), padd(v[0],v[4]));
    ull sm=pmul(pk1(C4), psub(v[0],v[4]));
    ull t1=pfma(pk1(C2),v[2], pmul(pk1( C6),v[6]));
    ull t2=pfma(pk1(C6),v[2], pmul(pk1(-C2),v[6]));
    ull E0=padd(sp,t1), E1=padd(sm,t2), E2=psub(sm,t2), E3=psub(sp,t1);
    ull O0=pfma(pk1(C1),v[1], pfma(pk1( C3),v[3], pfma(pk1( C5),v[5], pmul(pk1( C7),v[7]))));
    ull O1=pfma(pk1(C3),v[1], pfma(pk1(-C7),v[3], pfma(pk1(-C1),v[5], pmul(pk1(-C5),v[7]))));
    ull O2=pfma(pk1(C5),v[1], pfma(pk1(-C1),v[3], pfma(pk1( C7),v[5], pmul(pk1( C3),v[7]))));
    ull O3=pfma(pk1(C7),v[1], pfma(pk1(-C5),v[3], pfma(pk1( C3),v[5], pmul(pk1(-C1),v[7]))));
    v[0]=padd(E0,O0); v[7]=psub(E0,O0);
    v[1]=padd(E1,O1); v[6]=psub(E1,O1);
    v[2]=padd(E2,O2); v[5]=psub(E2,O2);
    v[3]=padd(E3,O3); v[4]=psub(E3,O3);
}

// smem layouts (verified conflict-free):
// Y  (float): row pitch 12 (float4-aligned), group pitch 104 (104%32==8 -> read banks 8g+r distinct)
// UV (ull)  : row pitch 10 (16B-aligned),    group pitch 84  (84%16==4  -> read bank-pairs 4g+r distinct per half-warp)
#define RPY 12
#define GPY 104
#define RPU 10
#define GPU 84

__device__ __forceinline__ void xposeYUV(float vy[8], ull uv[8],
                                         float* ybg, ull* uvbg, int r)
{
    float* yw = ybg + RPY * r;
    ull*   uw = uvbg + RPU * r;
    *(float4*)(yw)     = make_float4(vy[0], vy[1], vy[2], vy[3]);
    *(float4*)(yw + 4) = make_float4(vy[4], vy[5], vy[6], vy[7]);
    #pragma unroll
    for (int k = 0; k < 8; k += 2)
        *(ulonglong2*)(uw + k) = make_ulonglong2(uv[k], uv[k+1]);
    __syncwarp();
    #pragma unroll
    for (int k = 0; k < 8; ++k) {
        vy[k] = ybg[RPY * k + r];
        uv[k] = uvbg[RPU * k + r];
    }
    __syncwarp();
}

__global__ __launch_bounds__(256, 4)
void jpeg_roundtrip_kernel(const float* __restrict__ in, float* __restrict__ out)
{
    __shared__ __align__(16) float yb[8 * 4 * GPY];   // 13312 B
    __shared__ __align__(16) ull  uvb[8 * 4 * GPU];   // 21504 B
    __shared__ float qt[256];                         // interleaved (q, rq)

    const int tid  = threadIdx.x;
    const int warp = tid >> 5;
    const int lane = tid & 31;
    const int r    = lane >> 2;
    const int g    = lane & 3;

    {   // build interleaved quant table
        int w  = tid & 1, rr = (tid >> 1) & 7, ii = (tid >> 4) & 7, ch = tid >> 7;
        int si = ch * 64 + ii * 8 + rr;
        qt[tid] = w ? cRQf[si] : cQf[si];
    }

    float* ybg  = yb  + (warp * 4 + g) * GPY;
    ull*   uvbg = uvb + (warp * 4 + g) * GPU;

    const int x0   = blockIdx.x * 256 + (warp * 4 + g) * 8;
    const int y    = blockIdx.y * 8 + r;
    const int base = y * IMG_W + x0;

    // ---- load RGB ----
    const float4 Ra = *(const float4*)(in + base);
    const float4 Rb = *(const float4*)(in + base + 4);
    const float4 Ga = *(const float4*)(in + base + PLANE);
    const float4 Gb = *(const float4*)(in + base + PLANE + 4);
    const float4 Ba = *(const float4*)(in + base + 2*PLANE);
    const float4 Bb = *(const float4*)(in + base + 2*PLANE + 4);

    __syncthreads();   // quant table ready

    float R[8] = {Ra.x,Ra.y,Ra.z,Ra.w, Rb.x,Rb.y,Rb.z,Rb.w};
    float G[8] = {Ga.x,Ga.y,Ga.z,Ga.w, Gb.x,Gb.y,Gb.z,Gb.w};
    float B[8] = {Ba.x,Ba.y,Ba.z,Ba.w, Bb.x,Bb.y,Bb.z,Bb.w};

    // ---- forward color ----
    float vY[8];
    ull   pUV[8];
    #pragma unroll
    for (int k = 0; k < 8; ++k) {
        vY[k] = 0.299f*R[k] + 0.587f*G[k] + 0.114f*B[k];
        pUV[k] = pfma(pk1(R[k]), pk(-0.168736f, 0.5f),
                 pfma(pk1(G[k]), pk(-0.331264f, -0.418688f),
                 pfma(pk1(B[k]), pk(0.5f, -0.081312f), pk1(128.0f))));
    }

    // ---- DCT: row pass, transpose, column pass ----
    fdct8(vY); fdct8p(pUV);
    xposeYUV(vY, pUV, ybg, uvbg, r);
    fdct8(vY); fdct8p(pUV);

    // ---- quant/dequant: thread holds coeff [i][r] at index i ----
    #pragma unroll
    for (int i = 0; i < 8; ++i) {
        float2 qy = *(const float2*)(qt + i * 16 + r * 2);
        float2 qc = *(const float2*)(qt + 128 + i * 16 + r * 2);
        {   // luma (scalar)
            float sv = vY[i];
            float d  = sv * qy.y;
            float rn = rintf(d);
            float e  = fmaf(-rn, qy.x, sv) * qy.y;
            vY[i]    = fmaf(e*e, e, rn) * qy.x;
        }
        {   // chroma (packed pair, shared constants)
            float2 s = unpk(pUV[i]);
            float d0 = s.x * qc.y, d1 = s.y * qc.y;
            float r0 = rintf(d0), r1 = rintf(d1);
            float e0 = fmaf(-r0, qc.x, s.x) * qc.y;
            float e1 = fmaf(-r1, qc.x, s.y) * qc.y;
            pUV[i] = pk(fmaf(e0*e0, e0, r0) * qc.x,
                        fmaf(e1*e1, e1, r1) * qc.x);
        }
    }

    // ---- IDCT: column pass, transpose, row pass ----
    idct8(vY); idct8p(pUV);
    xposeYUV(vY, pUV, ybg, uvbg, r);
    idct8(vY); idct8p(pUV);

    // ---- inverse color + normalize + store ----
    #pragma unroll
    for (int h = 0; h < 2; ++h) {
        float4 Ro, Go, Bo;
        #pragma unroll
        for (int k = 0; k < 4; ++k) {
            int c = h*4 + k;
            float yv = vY[c];
            float2 uvv = unpk(pUV[c]);
            float u = uvv.x - 128.0f;
            float v = uvv.y - 128.0f;
            float Rv = fmaf(IW01, u, fmaf(IW02, v, yv));
            float Gv = fmaf(IW11, u, fmaf(IW12, v, yv));
            float Bv = fmaf(IW21, u, fmaf(IW22, v, yv));
            ((float*)&Ro)[k] = (Rv * (1.0f/255.0f) - MEAN0) * ISTD0;
            ((float*)&Go)[k] = (Gv * (1.0f/255.0f) - MEAN1) * ISTD1;
            ((float*)&Bo)[k] = (Bv * (1.0f/255.0f) - MEAN2) * ISTD2;
        }
        *(float4*)(out + base + h*4)           = Ro;
        *(float4*)(out + base + PLANE + h*4)   = Go;
        *(float4*)(out + base + 2*PLANE + h*4) = Bo;
    }
}

extern "C" void kernel_launch(void* const* d_in, const int* in_sizes, int n_in,
                              void* d_out, int out_size)
{
    const float* in = (const float*)d_in[0];
    float* out = (float*)d_out;
    dim3 grid(IMG_W / 256, IMG_H / 8);
    jpeg_roundtrip_kernel<<<grid, 256>>>(in, out);
}